// round 4
// baseline (speedup 1.0000x reference)
#include <cuda_runtime.h>

// Fixed dims
#define RVD 4
#define RD 16
#define F_IN 64
#define F_OUT 64
#define BVD 16              // B*V
#define ROWS_PER_BV 65536   // T*N*D
#define TILE 128
#define NTILES (ROWS_PER_BV / TILE)   // 512
#define BLOCK 256

// Per-bv factor, packed for f32x2 along the a-reduction:
// g_G1p[bv][(a2*16 + c)*2 + par] = G1[2*a2+par][c]
__device__ float g_G1p[BVD * RD * F_IN];

// smem: xs (TILE*64, swizzled f4 chunks) + ys (TILE*20) + g1p (1024)
#define YS_STRIDE 20
#define SMEM_FLOATS (TILE * 64 + TILE * YS_STRIDE + RD * F_IN)
#define SMEM_BYTES  (SMEM_FLOATS * 4)

typedef unsigned long long ull;

__device__ __forceinline__ void cp16(float* dst_smem, const float* src_gmem) {
    unsigned d = (unsigned)__cvta_generic_to_shared(dst_smem);
    asm volatile("cp.async.cg.shared.global [%0], [%1], 16;\n" :: "r"(d), "l"(src_gmem));
}
__device__ __forceinline__ void cp_commit_wait() {
    asm volatile("cp.async.commit_group;\n");
    asm volatile("cp.async.wait_group 0;\n");
}
__device__ __forceinline__ void ffma2(ull& acc, ull a, ull b) {
    asm("fma.rn.f32x2 %0, %1, %2, %0;" : "+l"(acc) : "l"(a), "l"(b));
}
__device__ __forceinline__ float pairsum(ull v) {
    float lo = __uint_as_float((unsigned)v);
    float hi = __uint_as_float((unsigned)(v >> 32));
    return lo + hi;
}
__device__ __forceinline__ ull pack2(float lo, float hi) {
    ull r;
    asm("mov.b64 %0, {%1, %2};" : "=l"(r) : "f"(lo), "f"(hi));
    return r;
}

// ---- prep: G1[a][c] = sum_B fac_in[B,a] * (sum_A fv[bv,A]*core[A,B,c]), packed pairs over a ----
__global__ void prep_kernel(const int* __restrict__ var_idx,
                            const float* __restrict__ core,
                            const float* __restrict__ factor_vars,
                            const float* __restrict__ fac_in) {
    int bv = blockIdx.x;     // 0..15
    int t = threadIdx.x;     // 0..63  (= 'a')
    __shared__ float W[RD][RD];
    int vi = var_idx[bv];

    #pragma unroll
    for (int kk = 0; kk < 4; kk++) {
        int idx = t * 4 + kk;
        int b = idx >> 4, c = idx & 15;
        float s = 0.f;
        #pragma unroll
        for (int A = 0; A < RVD; A++)
            s += factor_vars[vi * RVD + A] * core[(A * RD + b) * RD + c];
        W[b][c] = s;
    }
    __syncthreads();

    float fin[RD];
    #pragma unroll
    for (int b = 0; b < RD; b++) fin[b] = fac_in[b * F_IN + t];

    int a2 = t >> 1, par = t & 1;
    #pragma unroll
    for (int c = 0; c < RD; c++) {
        float s = 0.f;
        #pragma unroll
        for (int b = 0; b < RD; b++) s += fin[b] * W[b][c];
        g_G1p[bv * (RD * F_IN) + (a2 * RD + c) * 2 + par] = s;
    }
}

// ---------------- main ----------------
extern __shared__ float smem[];

__global__ __launch_bounds__(BLOCK, 4)
void tucker_main(const float* __restrict__ x,
                 const float* __restrict__ fac_out,
                 float* __restrict__ out) {
    float* xs  = smem;                       // TILE*64
    float* ys  = xs + TILE * 64;             // TILE*YS_STRIDE
    float* g1p = ys + TILE * YS_STRIDE;      // 1024

    const int tid  = threadIdx.x;
    const int bv   = blockIdx.y;
    const int tile = blockIdx.x;

    const size_t base = (size_t)bv * ROWS_PER_BV * 64 + (size_t)tile * TILE * 64;
    const float* xsrc = x + base;

    // ---- stage x tile (swizzled) + packed G1 via cp.async ----
    #pragma unroll
    for (int i = 0; i < 8; i++) {
        int fi = i * BLOCK + tid;            // float4 linear index in tile (128*16)
        int r = fi >> 4, c4 = fi & 15;
        int pos = r * 16 + (c4 ^ ((r >> 1) & 7));
        cp16(xs + (pos << 2), xsrc + (fi << 2));
    }
    cp16(g1p + (tid << 2), g_G1p + bv * (RD * F_IN) + (tid << 2));
    cp_commit_wait();
    __syncthreads();

    // ---- Y stage: thread = 2 rows x 4 c; f32x2 packed over the a-reduction ----
    {
        const int rg = tid >> 2;             // 0..63 -> rows rg*2, rg*2+1
        const int j4 = tid & 3;              // c block: c = j4*4 .. j4*4+3
        const int r0 = rg * 2;
        const int xkey = rg & 7;
        const ulonglong2* xs2  = reinterpret_cast<const ulonglong2*>(xs);   // 16B granules, 16 per row
        const ulonglong2* g1p2 = reinterpret_cast<const ulonglong2*>(g1p);  // 8 per a2-row

        // acc[r][c]: f32x2 partial sums (lo: even a, hi: odd a)
        ull a0c0 = 0, a0c1 = 0, a0c2 = 0, a0c3 = 0;
        ull a1c0 = 0, a1c1 = 0, a1c2 = 0, a1c3 = 0;

        #pragma unroll 4
        for (int k = 0; k < 16; k++) {
            int kk = k ^ xkey;
            // x pairs for 4 a's of this chunk: .x = {x[4k],x[4k+1]}, .y = {x[4k+2],x[4k+3]}
            ulonglong2 xA = xs2[(r0 + 0) * 16 + kk];   // row stride = 16 granules (64 floats)
            ulonglong2 xB = xs2[(r0 + 1) * 16 + kk];
            // G1p rows a2 = 2k (even pair) and 2k+1 (odd pair); 4 c-pairs each = 2 ull2
            int ga = (2 * k) * 8 + j4 * 2;        // ull2 index: a2*8 + (c/2 group)
            ulonglong2 gA0 = g1p2[ga];            // c = j4*4+0,1
            ulonglong2 gA1 = g1p2[ga + 1];        // c = j4*4+2,3
            ulonglong2 gB0 = g1p2[ga + 8];        // a2 = 2k+1
            ulonglong2 gB1 = g1p2[ga + 9];

            ffma2(a0c0, xA.x, gA0.x); ffma2(a0c1, xA.x, gA0.y);
            ffma2(a0c2, xA.x, gA1.x); ffma2(a0c3, xA.x, gA1.y);
            ffma2(a0c0, xA.y, gB0.x); ffma2(a0c1, xA.y, gB0.y);
            ffma2(a0c2, xA.y, gB1.x); ffma2(a0c3, xA.y, gB1.y);

            ffma2(a1c0, xB.x, gA0.x); ffma2(a1c1, xB.x, gA0.y);
            ffma2(a1c2, xB.x, gA1.x); ffma2(a1c3, xB.x, gA1.y);
            ffma2(a1c0, xB.y, gB0.x); ffma2(a1c1, xB.y, gB0.y);
            ffma2(a1c2, xB.y, gB1.x); ffma2(a1c3, xB.y, gB1.y);
        }
        *reinterpret_cast<float4*>(ys + (r0 + 0) * YS_STRIDE + j4 * 4) =
            make_float4(pairsum(a0c0), pairsum(a0c1), pairsum(a0c2), pairsum(a0c3));
        *reinterpret_cast<float4*>(ys + (r0 + 1) * YS_STRIDE + j4 * 4) =
            make_float4(pairsum(a1c0), pairsum(a1c1), pairsum(a1c2), pairsum(a1c3));
    }
    __syncthreads();

    // ---- out stage: thread owns 2 e-cols; f32x2 packed over the c-reduction ----
    {
        const int eg2 = tid & 31;            // e pair group: e = eg2*2, eg2*2+1
        const int rb  = tid >> 5;            // warp id 0..7
        const int e0  = eg2 * 2;

        // fop[e][c2] = {fac_out[2c2][e], fac_out[2c2+1][e]}
        ull fo0[8], fo1[8];
        #pragma unroll
        for (int c2 = 0; c2 < 8; c2++) {
            fo0[c2] = pack2(fac_out[(2 * c2) * F_OUT + e0],     fac_out[(2 * c2 + 1) * F_OUT + e0]);
            fo1[c2] = pack2(fac_out[(2 * c2) * F_OUT + e0 + 1], fac_out[(2 * c2 + 1) * F_OUT + e0 + 1]);
        }

        float2* ot = reinterpret_cast<float2*>(out + base);

        #pragma unroll 4
        for (int it = 0; it < 16; it++) {
            int r = rb + it * 8;
            const ulonglong2* yr = reinterpret_cast<const ulonglong2*>(ys + r * YS_STRIDE);
            ulonglong2 ya = yr[0];   // c pairs (0,1),(2,3)
            ulonglong2 yb = yr[1];   // (4,5),(6,7)
            ulonglong2 yc = yr[2];   // (8,9),(10,11)
            ulonglong2 yd = yr[3];   // (12,13),(14,15)

            ull s0 = 0, s1 = 0;
            ffma2(s0, ya.x, fo0[0]); ffma2(s1, ya.x, fo1[0]);
            ffma2(s0, ya.y, fo0[1]); ffma2(s1, ya.y, fo1[1]);
            ffma2(s0, yb.x, fo0[2]); ffma2(s1, yb.x, fo1[2]);
            ffma2(s0, yb.y, fo0[3]); ffma2(s1, yb.y, fo1[3]);
            ffma2(s0, yc.x, fo0[4]); ffma2(s1, yc.x, fo1[4]);
            ffma2(s0, yc.y, fo0[5]); ffma2(s1, yc.y, fo1[5]);
            ffma2(s0, yd.x, fo0[6]); ffma2(s1, yd.x, fo1[6]);
            ffma2(s0, yd.y, fo0[7]); ffma2(s1, yd.y, fo1[7]);

            ot[r * 32 + eg2] = make_float2(pairsum(s0), pairsum(s1));
        }
    }
}

extern "C" void kernel_launch(void* const* d_in, const int* in_sizes, int n_in,
                              void* d_out, int out_size) {
    const float* x           = (const float*)d_in[0];
    const int*   var_idx     = (const int*)d_in[1];
    const float* core        = (const float*)d_in[2];
    const float* factor_vars = (const float*)d_in[3];
    const float* fac_in      = (const float*)d_in[4];
    const float* fac_out     = (const float*)d_in[5];
    float* out = (float*)d_out;

    cudaFuncSetAttribute(tucker_main, cudaFuncAttributeMaxDynamicSharedMemorySize, SMEM_BYTES);

    prep_kernel<<<BVD, 64>>>(var_idx, core, factor_vars, fac_in);

    dim3 grid(NTILES, BVD);
    tucker_main<<<grid, BLOCK, SMEM_BYTES>>>(x, fac_out, out);
}

// round 5
// speedup vs baseline: 1.2157x; 1.2157x over previous
#include <cuda_runtime.h>

// Fixed dims
#define RVD 4
#define RD 16
#define F_IN 64
#define F_OUT 64
#define BVD 16              // B*V
#define ROWS_PER_BV 65536   // T*N*D
#define TILE 256
#define NTILES (ROWS_PER_BV / TILE)   // 256
#define BLOCK 256

// Per-bv factor, packed for f32x2 along the a-reduction:
// g_G1p[bv][(a2*16 + c)*2 + par] = G1[2*a2+par][c]   (a2 = a>>1, par = a&1)
__device__ float g_G1p[BVD * RD * F_IN];

// smem: xs (TILE*64, swizzled f4 chunks) + ys (TILE*20) + g1p (1024)
#define YS_STRIDE 20
#define SMEM_FLOATS (TILE * 64 + TILE * YS_STRIDE + RD * F_IN)
#define SMEM_BYTES  (SMEM_FLOATS * 4)

typedef unsigned long long ull;

__device__ __forceinline__ void cp16(float* dst_smem, const float* src_gmem) {
    unsigned d = (unsigned)__cvta_generic_to_shared(dst_smem);
    asm volatile("cp.async.cg.shared.global [%0], [%1], 16;\n" :: "r"(d), "l"(src_gmem));
}
__device__ __forceinline__ void cp_commit_wait() {
    asm volatile("cp.async.commit_group;\n");
    asm volatile("cp.async.wait_group 0;\n");
}
__device__ __forceinline__ void ffma2(ull& acc, ull a, ull b) {
    asm("fma.rn.f32x2 %0, %1, %2, %0;" : "+l"(acc) : "l"(a), "l"(b));
}
__device__ __forceinline__ float pairsum(ull v) {
    float lo = __uint_as_float((unsigned)v);
    float hi = __uint_as_float((unsigned)(v >> 32));
    return lo + hi;
}
__device__ __forceinline__ ull pack2(float lo, float hi) {
    ull r;
    asm("mov.b64 %0, {%1, %2};" : "=l"(r) : "f"(lo), "f"(hi));
    return r;
}

// ---- prep: G1[a][c] = sum_B fac_in[B,a] * (sum_A fv[bv,A]*core[A,B,c]), packed pairs over a ----
__global__ void prep_kernel(const int* __restrict__ var_idx,
                            const float* __restrict__ core,
                            const float* __restrict__ factor_vars,
                            const float* __restrict__ fac_in) {
    int bv = blockIdx.x;     // 0..15
    int t = threadIdx.x;     // 0..63  (= 'a')
    __shared__ float W[RD][RD];
    int vi = var_idx[bv];

    #pragma unroll
    for (int kk = 0; kk < 4; kk++) {
        int idx = t * 4 + kk;
        int b = idx >> 4, c = idx & 15;
        float s = 0.f;
        #pragma unroll
        for (int A = 0; A < RVD; A++)
            s += factor_vars[vi * RVD + A] * core[(A * RD + b) * RD + c];
        W[b][c] = s;
    }
    __syncthreads();

    float fin[RD];
    #pragma unroll
    for (int b = 0; b < RD; b++) fin[b] = fac_in[b * F_IN + t];

    int a2 = t >> 1, par = t & 1;
    #pragma unroll
    for (int c = 0; c < RD; c++) {
        float s = 0.f;
        #pragma unroll
        for (int b = 0; b < RD; b++) s += fin[b] * W[b][c];
        g_G1p[bv * (RD * F_IN) + (a2 * RD + c) * 2 + par] = s;
    }
}

// ---------------- main ----------------
extern __shared__ float smem[];

__global__ __launch_bounds__(BLOCK, 2)
void tucker_main(const float* __restrict__ x,
                 const float* __restrict__ fac_out,
                 float* __restrict__ out) {
    float* xs  = smem;                       // TILE*64
    float* ys  = xs + TILE * 64;             // TILE*YS_STRIDE
    float* g1p = ys + TILE * YS_STRIDE;      // 1024

    const int tid  = threadIdx.x;
    const int bv   = blockIdx.y;
    const int tile = blockIdx.x;

    const size_t base = (size_t)bv * ROWS_PER_BV * 64 + (size_t)tile * TILE * 64;
    const float* xsrc = x + base;

    // ---- stage x tile (swizzled) + packed G1 via cp.async ----
    #pragma unroll
    for (int i = 0; i < 16; i++) {
        int fi = i * BLOCK + tid;            // float4 linear index in tile (256*16)
        int r = fi >> 4, c4 = fi & 15;
        int pos = r * 16 + (c4 ^ ((r >> 2) & 7));
        cp16(xs + (pos << 2), xsrc + (fi << 2));
    }
    cp16(g1p + (tid << 2), g_G1p + bv * (RD * F_IN) + (tid << 2));
    cp_commit_wait();
    __syncthreads();

    // ---- Y stage: thread = 4 rows x 4 c; f32x2 packed over the a-reduction ----
    {
        const int rg = tid >> 2;             // 0..63 -> rows rg*4 .. rg*4+3
        const int j4 = tid & 3;              // c block: c = j4*4 .. j4*4+3
        const int r0 = rg * 4;
        const int key = rg & 7;              // = (r>>2)&7 for all 4 rows of this thread
        const ulonglong2* xs2  = reinterpret_cast<const ulonglong2*>(xs);   // 16 granules/row
        const ulonglong2* g1p2 = reinterpret_cast<const ulonglong2*>(g1p);  // 8 granules per a2-row

        // acc[row][c] : f32x2 partial sums (lo: even a, hi: odd a)
        ull a0c0=0,a0c1=0,a0c2=0,a0c3=0;
        ull a1c0=0,a1c1=0,a1c2=0,a1c3=0;
        ull a2c0=0,a2c1=0,a2c2=0,a2c3=0;
        ull a3c0=0,a3c1=0,a3c2=0,a3c3=0;

        #pragma unroll 4
        for (int k = 0; k < 16; k++) {
            int kk = k ^ key;
            // x pairs: .x = {x[4k],x[4k+1]}, .y = {x[4k+2],x[4k+3]}
            ulonglong2 x0 = xs2[(r0 + 0) * 16 + kk];
            ulonglong2 x1 = xs2[(r0 + 1) * 16 + kk];
            ulonglong2 x2 = xs2[(r0 + 2) * 16 + kk];
            ulonglong2 x3 = xs2[(r0 + 3) * 16 + kk];
            // G1p rows a2 = 2k (pairs a=4k,4k+1) and a2 = 2k+1 (pairs a=4k+2,4k+3)
            int ga = k * 16 + j4 * 2;             // (2k)*8 + j4*2, ull2 units
            ulonglong2 gA0 = g1p2[ga];            // a2=2k,   c = j4*4+0,1
            ulonglong2 gA1 = g1p2[ga + 1];        //          c = j4*4+2,3
            ulonglong2 gB0 = g1p2[ga + 8];        // a2=2k+1, c = j4*4+0,1
            ulonglong2 gB1 = g1p2[ga + 9];

            ffma2(a0c0, x0.x, gA0.x); ffma2(a0c1, x0.x, gA0.y);
            ffma2(a0c2, x0.x, gA1.x); ffma2(a0c3, x0.x, gA1.y);
            ffma2(a0c0, x0.y, gB0.x); ffma2(a0c1, x0.y, gB0.y);
            ffma2(a0c2, x0.y, gB1.x); ffma2(a0c3, x0.y, gB1.y);

            ffma2(a1c0, x1.x, gA0.x); ffma2(a1c1, x1.x, gA0.y);
            ffma2(a1c2, x1.x, gA1.x); ffma2(a1c3, x1.x, gA1.y);
            ffma2(a1c0, x1.y, gB0.x); ffma2(a1c1, x1.y, gB0.y);
            ffma2(a1c2, x1.y, gB1.x); ffma2(a1c3, x1.y, gB1.y);

            ffma2(a2c0, x2.x, gA0.x); ffma2(a2c1, x2.x, gA0.y);
            ffma2(a2c2, x2.x, gA1.x); ffma2(a2c3, x2.x, gA1.y);
            ffma2(a2c0, x2.y, gB0.x); ffma2(a2c1, x2.y, gB0.y);
            ffma2(a2c2, x2.y, gB1.x); ffma2(a2c3, x2.y, gB1.y);

            ffma2(a3c0, x3.x, gA0.x); ffma2(a3c1, x3.x, gA0.y);
            ffma2(a3c2, x3.x, gA1.x); ffma2(a3c3, x3.x, gA1.y);
            ffma2(a3c0, x3.y, gB0.x); ffma2(a3c1, x3.y, gB0.y);
            ffma2(a3c2, x3.y, gB1.x); ffma2(a3c3, x3.y, gB1.y);
        }
        *reinterpret_cast<float4*>(ys + (r0 + 0) * YS_STRIDE + j4 * 4) =
            make_float4(pairsum(a0c0), pairsum(a0c1), pairsum(a0c2), pairsum(a0c3));
        *reinterpret_cast<float4*>(ys + (r0 + 1) * YS_STRIDE + j4 * 4) =
            make_float4(pairsum(a1c0), pairsum(a1c1), pairsum(a1c2), pairsum(a1c3));
        *reinterpret_cast<float4*>(ys + (r0 + 2) * YS_STRIDE + j4 * 4) =
            make_float4(pairsum(a2c0), pairsum(a2c1), pairsum(a2c2), pairsum(a2c3));
        *reinterpret_cast<float4*>(ys + (r0 + 3) * YS_STRIDE + j4 * 4) =
            make_float4(pairsum(a3c0), pairsum(a3c1), pairsum(a3c2), pairsum(a3c3));
    }
    __syncthreads();

    // ---- out stage: thread owns 2 e-cols; f32x2 packed over the c-reduction ----
    {
        const int eg2 = tid & 31;            // e pair: e = eg2*2, eg2*2+1
        const int rb  = tid >> 5;            // warp id 0..7
        const int e0  = eg2 * 2;

        // fo[e][c2] = {fac_out[2c2][e], fac_out[2c2+1][e]}
        ull fo0[8], fo1[8];
        #pragma unroll
        for (int c2 = 0; c2 < 8; c2++) {
            fo0[c2] = pack2(fac_out[(2 * c2) * F_OUT + e0],     fac_out[(2 * c2 + 1) * F_OUT + e0]);
            fo1[c2] = pack2(fac_out[(2 * c2) * F_OUT + e0 + 1], fac_out[(2 * c2 + 1) * F_OUT + e0 + 1]);
        }

        float2* ot = reinterpret_cast<float2*>(out + base);

        #pragma unroll 4
        for (int it = 0; it < 32; it++) {
            int r = rb + it * 8;
            const ulonglong2* yr = reinterpret_cast<const ulonglong2*>(ys + r * YS_STRIDE);
            ulonglong2 ya = yr[0];   // c pairs (0,1),(2,3)
            ulonglong2 yb = yr[1];   // (4,5),(6,7)
            ulonglong2 yc = yr[2];   // (8,9),(10,11)
            ulonglong2 yd = yr[3];   // (12,13),(14,15)

            ull s0 = 0, s1 = 0;
            ffma2(s0, ya.x, fo0[0]); ffma2(s1, ya.x, fo1[0]);
            ffma2(s0, ya.y, fo0[1]); ffma2(s1, ya.y, fo1[1]);
            ffma2(s0, yb.x, fo0[2]); ffma2(s1, yb.x, fo1[2]);
            ffma2(s0, yb.y, fo0[3]); ffma2(s1, yb.y, fo1[3]);
            ffma2(s0, yc.x, fo0[4]); ffma2(s1, yc.x, fo1[4]);
            ffma2(s0, yc.y, fo0[5]); ffma2(s1, yc.y, fo1[5]);
            ffma2(s0, yd.x, fo0[6]); ffma2(s1, yd.x, fo1[6]);
            ffma2(s0, yd.y, fo0[7]); ffma2(s1, yd.y, fo1[7]);

            ot[r * 32 + eg2] = make_float2(pairsum(s0), pairsum(s1));
        }
    }
}

extern "C" void kernel_launch(void* const* d_in, const int* in_sizes, int n_in,
                              void* d_out, int out_size) {
    const float* x           = (const float*)d_in[0];
    const int*   var_idx     = (const int*)d_in[1];
    const float* core        = (const float*)d_in[2];
    const float* factor_vars = (const float*)d_in[3];
    const float* fac_in      = (const float*)d_in[4];
    const float* fac_out     = (const float*)d_in[5];
    float* out = (float*)d_out;

    cudaFuncSetAttribute(tucker_main, cudaFuncAttributeMaxDynamicSharedMemorySize, SMEM_BYTES);

    prep_kernel<<<BVD, 64>>>(var_idx, core, factor_vars, fac_in);

    dim3 grid(NTILES, BVD);
    tucker_main<<<grid, BLOCK, SMEM_BYTES>>>(x, fac_out, out);
}

// round 6
// speedup vs baseline: 1.3036x; 1.0723x over previous
#include <cuda_runtime.h>

// Fixed dims
#define RVD 4
#define RD 16
#define F_IN 64
#define F_OUT 64
#define BVD 16              // B*V
#define ROWS_PER_BV 65536   // T*N*D
#define TILE 128
#define NTILES (ROWS_PER_BV / TILE)   // 512
#define BLOCK 128

// Per-bv factor, packed for f32x2 along the a-reduction:
// g_G1p[bv][(a2*16 + c)*2 + par] = G1[2*a2+par][c]   (a2 = a>>1, par = a&1)
__device__ float g_G1p[BVD * RD * F_IN];

// smem: xs (TILE*64, swizzled f4 chunks) + ys (TILE*20) + g1p (1024)
#define YS_STRIDE 20
#define SMEM_FLOATS (TILE * 64 + TILE * YS_STRIDE + RD * F_IN)
#define SMEM_BYTES  (SMEM_FLOATS * 4)          // 47104 B -> 4 CTAs/SM

typedef unsigned long long ull;

__device__ __forceinline__ void cp16(float* dst_smem, const float* src_gmem) {
    unsigned d = (unsigned)__cvta_generic_to_shared(dst_smem);
    asm volatile("cp.async.cg.shared.global [%0], [%1], 16;\n" :: "r"(d), "l"(src_gmem));
}
__device__ __forceinline__ void cp_commit_wait() {
    asm volatile("cp.async.commit_group;\n");
    asm volatile("cp.async.wait_group 0;\n");
}
__device__ __forceinline__ void ffma2(ull& acc, ull a, ull b) {
    asm("fma.rn.f32x2 %0, %1, %2, %0;" : "+l"(acc) : "l"(a), "l"(b));
}
__device__ __forceinline__ float pairsum(ull v) {
    float lo = __uint_as_float((unsigned)v);
    float hi = __uint_as_float((unsigned)(v >> 32));
    return lo + hi;
}
__device__ __forceinline__ ull pack2(float lo, float hi) {
    ull r;
    asm("mov.b64 %0, {%1, %2};" : "=l"(r) : "f"(lo), "f"(hi));
    return r;
}

// ---- prep: G1[a][c] = sum_B fac_in[B,a] * (sum_A fv[bv,A]*core[A,B,c]), packed pairs over a ----
__global__ void prep_kernel(const int* __restrict__ var_idx,
                            const float* __restrict__ core,
                            const float* __restrict__ factor_vars,
                            const float* __restrict__ fac_in) {
    int bv = blockIdx.x;     // 0..15
    int t = threadIdx.x;     // 0..63  (= 'a')
    __shared__ float W[RD][RD];
    int vi = var_idx[bv];

    #pragma unroll
    for (int kk = 0; kk < 4; kk++) {
        int idx = t * 4 + kk;
        int b = idx >> 4, c = idx & 15;
        float s = 0.f;
        #pragma unroll
        for (int A = 0; A < RVD; A++)
            s += factor_vars[vi * RVD + A] * core[(A * RD + b) * RD + c];
        W[b][c] = s;
    }
    __syncthreads();

    float fin[RD];
    #pragma unroll
    for (int b = 0; b < RD; b++) fin[b] = fac_in[b * F_IN + t];

    int a2 = t >> 1, par = t & 1;
    #pragma unroll
    for (int c = 0; c < RD; c++) {
        float s = 0.f;
        #pragma unroll
        for (int b = 0; b < RD; b++) s += fin[b] * W[b][c];
        g_G1p[bv * (RD * F_IN) + (a2 * RD + c) * 2 + par] = s;
    }
}

// ---------------- main ----------------
extern __shared__ float smem[];

__global__ __launch_bounds__(BLOCK, 4)
void tucker_main(const float* __restrict__ x,
                 const float* __restrict__ fac_out,
                 float* __restrict__ out) {
    float* xs  = smem;                       // TILE*64
    float* ys  = xs + TILE * 64;             // TILE*YS_STRIDE
    float* g1p = ys + TILE * YS_STRIDE;      // 1024

    const int tid  = threadIdx.x;
    const int bv   = blockIdx.y;
    const int tile = blockIdx.x;

    const size_t base = (size_t)bv * ROWS_PER_BV * 64 + (size_t)tile * TILE * 64;
    const float* xsrc = x + base;

    // ---- stage x tile (swizzled) + packed G1 via cp.async ----
    #pragma unroll
    for (int i = 0; i < 16; i++) {
        int fi = i * BLOCK + tid;            // float4 linear index in tile (128*16)
        int r = fi >> 4, c4 = fi & 15;
        int pos = r * 16 + (c4 ^ ((r >> 2) & 7));
        cp16(xs + (pos << 2), xsrc + (fi << 2));
    }
    cp16(g1p + tid * 8,     g_G1p + bv * (RD * F_IN) + tid * 8);
    cp16(g1p + tid * 8 + 4, g_G1p + bv * (RD * F_IN) + tid * 8 + 4);
    cp_commit_wait();
    __syncthreads();

    // ---- Y stage: thread = 4 rows x 4 c; f32x2 packed over the a-reduction ----
    {
        const int rg = tid >> 2;             // 0..31 -> rows rg*4 .. rg*4+3
        const int j4 = tid & 3;              // c block: c = j4*4 .. j4*4+3
        const int r0 = rg * 4;
        const int key = rg & 7;              // = (r>>2)&7 for all 4 rows of this thread
        const ulonglong2* xs2  = reinterpret_cast<const ulonglong2*>(xs);   // 16 granules/row
        const ulonglong2* g1p2 = reinterpret_cast<const ulonglong2*>(g1p);  // 8 granules per a2-row

        ull a0c0=0,a0c1=0,a0c2=0,a0c3=0;
        ull a1c0=0,a1c1=0,a1c2=0,a1c3=0;
        ull a2c0=0,a2c1=0,a2c2=0,a2c3=0;
        ull a3c0=0,a3c1=0,a3c2=0,a3c3=0;

        #pragma unroll 4
        for (int k = 0; k < 16; k++) {
            int kk = k ^ key;
            ulonglong2 x0 = xs2[(r0 + 0) * 16 + kk];
            ulonglong2 x1 = xs2[(r0 + 1) * 16 + kk];
            ulonglong2 x2 = xs2[(r0 + 2) * 16 + kk];
            ulonglong2 x3 = xs2[(r0 + 3) * 16 + kk];
            int ga = k * 16 + j4 * 2;             // (2k)*8 + j4*2, ull2 units
            ulonglong2 gA0 = g1p2[ga];            // a2=2k,   c = j4*4+0,1
            ulonglong2 gA1 = g1p2[ga + 1];        //          c = j4*4+2,3
            ulonglong2 gB0 = g1p2[ga + 8];        // a2=2k+1
            ulonglong2 gB1 = g1p2[ga + 9];

            ffma2(a0c0, x0.x, gA0.x); ffma2(a0c1, x0.x, gA0.y);
            ffma2(a0c2, x0.x, gA1.x); ffma2(a0c3, x0.x, gA1.y);
            ffma2(a0c0, x0.y, gB0.x); ffma2(a0c1, x0.y, gB0.y);
            ffma2(a0c2, x0.y, gB1.x); ffma2(a0c3, x0.y, gB1.y);

            ffma2(a1c0, x1.x, gA0.x); ffma2(a1c1, x1.x, gA0.y);
            ffma2(a1c2, x1.x, gA1.x); ffma2(a1c3, x1.x, gA1.y);
            ffma2(a1c0, x1.y, gB0.x); ffma2(a1c1, x1.y, gB0.y);
            ffma2(a1c2, x1.y, gB1.x); ffma2(a1c3, x1.y, gB1.y);

            ffma2(a2c0, x2.x, gA0.x); ffma2(a2c1, x2.x, gA0.y);
            ffma2(a2c2, x2.x, gA1.x); ffma2(a2c3, x2.x, gA1.y);
            ffma2(a2c0, x2.y, gB0.x); ffma2(a2c1, x2.y, gB0.y);
            ffma2(a2c2, x2.y, gB1.x); ffma2(a2c3, x2.y, gB1.y);

            ffma2(a3c0, x3.x, gA0.x); ffma2(a3c1, x3.x, gA0.y);
            ffma2(a3c2, x3.x, gA1.x); ffma2(a3c3, x3.x, gA1.y);
            ffma2(a3c0, x3.y, gB0.x); ffma2(a3c1, x3.y, gB0.y);
            ffma2(a3c2, x3.y, gB1.x); ffma2(a3c3, x3.y, gB1.y);
        }
        *reinterpret_cast<float4*>(ys + (r0 + 0) * YS_STRIDE + j4 * 4) =
            make_float4(pairsum(a0c0), pairsum(a0c1), pairsum(a0c2), pairsum(a0c3));
        *reinterpret_cast<float4*>(ys + (r0 + 1) * YS_STRIDE + j4 * 4) =
            make_float4(pairsum(a1c0), pairsum(a1c1), pairsum(a1c2), pairsum(a1c3));
        *reinterpret_cast<float4*>(ys + (r0 + 2) * YS_STRIDE + j4 * 4) =
            make_float4(pairsum(a2c0), pairsum(a2c1), pairsum(a2c2), pairsum(a2c3));
        *reinterpret_cast<float4*>(ys + (r0 + 3) * YS_STRIDE + j4 * 4) =
            make_float4(pairsum(a3c0), pairsum(a3c1), pairsum(a3c2), pairsum(a3c3));
    }
    __syncthreads();

    // ---- out stage: thread owns 4 e-cols; f32x2 packed over the c-reduction ----
    {
        const int eg = tid & 15;             // e group: e = eg*4 .. eg*4+3
        const int rs = tid >> 4;             // row slot 0..7
        const int e0 = eg * 4;

        // fo[el][c2] = {fac_out[2c2][e0+el], fac_out[2c2+1][e0+el]}
        ull fo0[8], fo1[8], fo2[8], fo3[8];
        #pragma unroll
        for (int c2 = 0; c2 < 8; c2++) {
            const float* fa = fac_out + (2 * c2) * F_OUT + e0;
            const float* fb = fac_out + (2 * c2 + 1) * F_OUT + e0;
            fo0[c2] = pack2(fa[0], fb[0]);
            fo1[c2] = pack2(fa[1], fb[1]);
            fo2[c2] = pack2(fa[2], fb[2]);
            fo3[c2] = pack2(fa[3], fb[3]);
        }

        float4* ot = reinterpret_cast<float4*>(out + base);

        #pragma unroll 4
        for (int it = 0; it < 16; it++) {
            int r = rs + it * 8;
            const ulonglong2* yr = reinterpret_cast<const ulonglong2*>(ys + r * YS_STRIDE);
            ulonglong2 ya = yr[0];   // c pairs (0,1),(2,3)
            ulonglong2 yb = yr[1];   // (4,5),(6,7)
            ulonglong2 yc = yr[2];   // (8,9),(10,11)
            ulonglong2 yd = yr[3];   // (12,13),(14,15)

            ull s0 = 0, s1 = 0, s2 = 0, s3 = 0;
            ffma2(s0, ya.x, fo0[0]); ffma2(s1, ya.x, fo1[0]); ffma2(s2, ya.x, fo2[0]); ffma2(s3, ya.x, fo3[0]);
            ffma2(s0, ya.y, fo0[1]); ffma2(s1, ya.y, fo1[1]); ffma2(s2, ya.y, fo2[1]); ffma2(s3, ya.y, fo3[1]);
            ffma2(s0, yb.x, fo0[2]); ffma2(s1, yb.x, fo1[2]); ffma2(s2, yb.x, fo2[2]); ffma2(s3, yb.x, fo3[2]);
            ffma2(s0, yb.y, fo0[3]); ffma2(s1, yb.y, fo1[3]); ffma2(s2, yb.y, fo2[3]); ffma2(s3, yb.y, fo3[3]);
            ffma2(s0, yc.x, fo0[4]); ffma2(s1, yc.x, fo1[4]); ffma2(s2, yc.x, fo2[4]); ffma2(s3, yc.x, fo3[4]);
            ffma2(s0, yc.y, fo0[5]); ffma2(s1, yc.y, fo1[5]); ffma2(s2, yc.y, fo2[5]); ffma2(s3, yc.y, fo3[5]);
            ffma2(s0, yd.x, fo0[6]); ffma2(s1, yd.x, fo1[6]); ffma2(s2, yd.x, fo2[6]); ffma2(s3, yd.x, fo3[6]);
            ffma2(s0, yd.y, fo0[7]); ffma2(s1, yd.y, fo1[7]); ffma2(s2, yd.y, fo2[7]); ffma2(s3, yd.y, fo3[7]);

            ot[r * 16 + eg] = make_float4(pairsum(s0), pairsum(s1), pairsum(s2), pairsum(s3));
        }
    }
}

extern "C" void kernel_launch(void* const* d_in, const int* in_sizes, int n_in,
                              void* d_out, int out_size) {
    const float* x           = (const float*)d_in[0];
    const int*   var_idx     = (const int*)d_in[1];
    const float* core        = (const float*)d_in[2];
    const float* factor_vars = (const float*)d_in[3];
    const float* fac_in      = (const float*)d_in[4];
    const float* fac_out     = (const float*)d_in[5];
    float* out = (float*)d_out;

    cudaFuncSetAttribute(tucker_main, cudaFuncAttributeMaxDynamicSharedMemorySize, SMEM_BYTES);

    prep_kernel<<<BVD, 64>>>(var_idx, core, factor_vars, fac_in);

    dim3 grid(NTILES, BVD);
    tucker_main<<<grid, BLOCK, SMEM_BYTES>>>(x, fac_out, out);
}